// round 4
// baseline (speedup 1.0000x reference)
#include <cuda_runtime.h>
#include <math.h>

// Shapes fixed per reference: B=8192, D=128, R=64, C=64
// exp(logits) underflows to exact 0 for all but ~4000 of 524288 (b,r) pairs
// (logit ~ N(-170, 27.5), threshold ~ -104). Compute frs exactly, compact
// nonzero pairs per rule, and run a gathered per-rule GEMV with W staged in
// smem once per block (W traffic 4 MB total, not 128 MB).

// ---------------- device scratch ----------------
__device__ float  g_psum[128 * 512];     // BN partial sums, transposed: [d][blk]
__device__ float  g_psq [128 * 512];     // BN partial sumsq: [d][blk]
__device__ float2 g_scsh[128];           // per-d (scale, shift)
__device__ float4 g_coef[128 * 32];      // [d][lane] = (u_l, m_l, u_l+32, m_l+32); u=1/(2s^2), m=-2cu
__device__ float  g_csum[64];            // per-rule sum_d c^2 u
__device__ int    g_count[64];           // nonzero rows per rule
__device__ int    g_rows [64 * 8192];
__device__ float  g_fvals[64 * 8192];

// ---------------- kA: zero out + BN partials + coef pack + counter reset ----------------
// grid 512, block 256
__global__ void kA_prep(const float* __restrict__ x,
                        const float* __restrict__ centers,
                        const float* __restrict__ sigmas,
                        float4* __restrict__ out4) {
    int blk = blockIdx.x, tid = threadIdx.x;

    // zero output: 131072 float4 / 512 blocks = 1 per thread
    out4[blk * 256 + tid] = make_float4(0.f, 0.f, 0.f, 0.f);

    if (blk == 0 && tid < 64) {
        g_count[tid] = 0;
        // per-rule csum = sum_d c^2 * u
        float cs = 0.f;
        for (int d = 0; d < 128; ++d) {
            float c = centers[d * 64 + tid];
            float s = sigmas [d * 64 + tid];
            float u = 1.0f / (2.0f * s * s);
            cs = fmaf(c * c, u, cs);
        }
        g_csum[tid] = cs;
    }

    // pack quadratic coefficients: 4096 float4 total, 8 per block
    if (tid < 8) {
        int f = blk * 8 + tid;           // f = d*32 + lane
        int d = f >> 5, ln = f & 31;
        float c0 = centers[d * 64 + ln],      s0 = sigmas[d * 64 + ln];
        float c1 = centers[d * 64 + ln + 32], s1 = sigmas[d * 64 + ln + 32];
        float u0 = 1.0f / (2.0f * s0 * s0);
        float u1 = 1.0f / (2.0f * s1 * s1);
        g_coef[f] = make_float4(u0, -2.0f * c0 * u0, u1, -2.0f * c1 * u1);
    }

    // BN partial sums over rows [blk*16, blk*16+16)
    const float* xp = x + (size_t)blk * 16 * 128;
    float s = 0.f, s2 = 0.f;
    #pragma unroll
    for (int it = 0; it < 8; ++it) {
        float v = xp[it * 256 + tid];    // d = tid & 127, invariant over it
        s += v; s2 += v * v;
    }
    __shared__ float ps[256], ps2[256];
    ps[tid] = s; ps2[tid] = s2;
    __syncthreads();
    if (tid < 128) {
        g_psum[tid * 512 + blk] = ps[tid] + ps[tid + 128];   // [d][blk]
        g_psq [tid * 512 + blk] = ps2[tid] + ps2[tid + 128];
    }
}

// ---------------- kC: firing strengths + per-rule compaction (+ BN finalize in block 0) ----------------
// grid 444, block 256 (8 warps). smem: coef copy [d][lane] float4 = 64KB.
// Each warp iteration processes a pair of rows sharing coefficient loads.
__global__ void kC_frs(const float* __restrict__ x,
                       const float* __restrict__ rule_masks,
                       const float* __restrict__ gamma,
                       const float* __restrict__ beta) {
    extern __shared__ float4 cs4[];      // 4096 float4
    int tid = threadIdx.x;

    // Block 0 finalizes BN stats (consumed only by kD, which launches later).
    if (blockIdx.x == 0) {
        int d = tid >> 1, half = tid & 1;
        const float4* p4 = (const float4*)(g_psum + d * 512 + half * 256);
        const float4* q4 = (const float4*)(g_psq  + d * 512 + half * 256);
        float s = 0.f, s2 = 0.f;
        #pragma unroll 8
        for (int k = 0; k < 64; ++k) {
            float4 a = p4[k]; s  += (a.x + a.y) + (a.z + a.w);
            float4 b = q4[k]; s2 += (b.x + b.y) + (b.z + b.w);
        }
        s  += __shfl_xor_sync(0xffffffffu, s,  1);
        s2 += __shfl_xor_sync(0xffffffffu, s2, 1);
        if (half == 0) {
            float mean = s  * (1.0f / 8192.0f);
            float var  = s2 * (1.0f / 8192.0f) - mean * mean;
            var = fmaxf(var, 0.0f);
            float sc = gamma[d] / sqrtf(var + 1e-5f);
            g_scsh[d] = make_float2(sc, beta[d] - mean * sc);
        }
    }

    const float4* gc = g_coef;
    for (int k = tid; k < 4096; k += 256) cs4[k] = gc[k];
    __syncthreads();

    int lane = tid & 31, wid = tid >> 5;
    float m0 = rule_masks[lane];
    float m1 = rule_masks[lane + 32];
    float cs0 = g_csum[lane];
    float cs1 = g_csum[lane + 32];
    int w = blockIdx.x * 8 + wid;        // global warp id, [0, 3552)

    for (int p = w; p < 4096; p += 3552) {
        int b0 = 2 * p, b1 = 2 * p + 1;
        const float* xr0 = x + (size_t)b0 * 128;
        const float* xr1 = x + (size_t)b1 * 128;
        float xq0[4], xq1[4];
        #pragma unroll
        for (int j = 0; j < 4; ++j) {
            xq0[j] = xr0[j * 32 + lane];
            xq1[j] = xr1[j * 32 + lane];
        }
        float a00 = 0.f, a01 = 0.f, a10 = 0.f, a11 = 0.f;
        #pragma unroll
        for (int j = 0; j < 4; ++j) {
            float xv0 = xq0[j], xv1 = xq1[j];
            #pragma unroll 8
            for (int t = 0; t < 32; ++t) {
                float xd0 = __shfl_sync(0xffffffffu, xv0, t);
                float xd1 = __shfl_sync(0xffffffffu, xv1, t);
                float x20 = xd0 * xd0;
                float x21 = xd1 * xd1;
                float4 cf = cs4[(j * 32 + t) * 32 + lane];
                a00 = fmaf(x20, cf.x, a00); a00 = fmaf(xd0, cf.y, a00);
                a01 = fmaf(x20, cf.z, a01); a01 = fmaf(xd0, cf.w, a01);
                a10 = fmaf(x21, cf.x, a10); a10 = fmaf(xd1, cf.y, a10);
                a11 = fmaf(x21, cf.z, a11); a11 = fmaf(xd1, cf.w, a11);
            }
        }
        float r00 = expf(-(a00 + cs0)) * m0, r01 = expf(-(a01 + cs1)) * m1;
        float r10 = expf(-(a10 + cs0)) * m0, r11 = expf(-(a11 + cs1)) * m1;
        float s0 = r00 + r01, s1 = r10 + r11;
        #pragma unroll
        for (int off = 16; off; off >>= 1) {
            s0 += __shfl_xor_sync(0xffffffffu, s0, off);
            s1 += __shfl_xor_sync(0xffffffffu, s1, off);
        }
        float den0 = s0 + 1e-10f, den1 = s1 + 1e-10f;
        float f00 = r00 / den0, f01 = r01 / den0;
        float f10 = r10 / den1, f11 = r11 / den1;
        if (f00 > 0.f) { int q = atomicAdd(&g_count[lane], 1);
                         g_rows[lane * 8192 + q] = b0; g_fvals[lane * 8192 + q] = f00; }
        if (f01 > 0.f) { int q = atomicAdd(&g_count[lane + 32], 1);
                         g_rows[(lane + 32) * 8192 + q] = b0; g_fvals[(lane + 32) * 8192 + q] = f01; }
        if (f10 > 0.f) { int q = atomicAdd(&g_count[lane], 1);
                         g_rows[lane * 8192 + q] = b1; g_fvals[lane * 8192 + q] = f10; }
        if (f11 > 0.f) { int q = atomicAdd(&g_count[lane + 32], 1);
                         g_rows[(lane + 32) * 8192 + q] = b1; g_fvals[(lane + 32) * 8192 + q] = f11; }
    }
}

// ---------------- kD: per-rule gathered GEMV, W staged in smem ----------------
// grid (2, 64), block 256 (8 warps). Warp handles rows i = bx*8+wid, stride 16.
// Lane covers 2 output cols; per k: 1 shfl + 1 LDS.64 + 2 FMA.
__global__ void kD_out(const float* __restrict__ x,
                       const float* __restrict__ weights,
                       const float* __restrict__ biases,
                       float* __restrict__ out) {
    int r = blockIdx.y;
    __shared__ float4 Ws4[2048];         // W[r]: [128][64] floats = 32KB
    __shared__ float2 scsh[128];
    __shared__ float  bias_s[64];
    int tid = threadIdx.x;
    const float4* Wg = (const float4*)(weights + (size_t)r * 8192);
    #pragma unroll
    for (int k = 0; k < 8; ++k) Ws4[k * 256 + tid] = Wg[k * 256 + tid];
    if (tid < 128) scsh[tid] = g_scsh[tid];
    if (tid < 64)  bias_s[tid] = biases[r * 64 + tid];
    __syncthreads();

    int cnt = g_count[r];
    const float* Ws = (const float*)Ws4;
    int lane = tid & 31, wid = tid >> 5;
    int c = lane * 2;

    for (int i = blockIdx.x * 8 + wid; i < cnt; i += 16) {
        int b   = g_rows [r * 8192 + i];
        float f = g_fvals[r * 8192 + i];
        float xnv[4];
        #pragma unroll
        for (int j = 0; j < 4; ++j) {
            float2 ss = scsh[j * 32 + lane];
            xnv[j] = x[(size_t)b * 128 + j * 32 + lane] * ss.x + ss.y;
        }
        float a0 = 0.f, a1 = 0.f;
        #pragma unroll
        for (int j = 0; j < 4; ++j) {
            float xv = xnv[j];
            #pragma unroll 8
            for (int t = 0; t < 32; ++t) {
                float xk = __shfl_sync(0xffffffffu, xv, t);
                float2 w = *(const float2*)(Ws + (j * 32 + t) * 64 + c);
                a0 = fmaf(xk, w.x, a0);
                a1 = fmaf(xk, w.y, a1);
            }
        }
        atomicAdd(out + (size_t)b * 64 + c,     f * (a0 + bias_s[c]));
        atomicAdd(out + (size_t)b * 64 + c + 1, f * (a1 + bias_s[c + 1]));
    }
}

// ---------------- launch ----------------
extern "C" void kernel_launch(void* const* d_in, const int* in_sizes, int n_in,
                              void* d_out, int out_size) {
    const float* x       = (const float*)d_in[0];
    const float* centers = (const float*)d_in[1];
    const float* sigmas  = (const float*)d_in[2];
    const float* weights = (const float*)d_in[3];
    const float* biases  = (const float*)d_in[4];
    const float* gamma   = (const float*)d_in[5];
    const float* beta    = (const float*)d_in[6];
    const float* masks   = (const float*)d_in[7];
    float* out = (float*)d_out;

    cudaFuncSetAttribute(kC_frs, cudaFuncAttributeMaxDynamicSharedMemorySize, 65536);

    kA_prep<<<512, 256>>>(x, centers, sigmas, (float4*)out);
    kC_frs<<<444, 256, 65536>>>(x, masks, gamma, beta);
    dim3 gD(2, 64);
    kD_out<<<gD, 256>>>(x, weights, biases, out);
}